// round 12
// baseline (speedup 1.0000x reference)
#include <cuda_runtime.h>
#include <cstdint>

// FieldAwareFM: B=16384, F=10 fields, D=8.
// y[b] = b_lin + sum_f w[xoff[b,f]] + sum_{f<g} <emb[f, xoff[b,g]], emb[g, xoff[b,f]]>
//
// Combination of the two best measured configurations:
//  - fields 4..9 packed into 320B per-column blocks (9 rows + folded w):
//    rows keyed by a small-field index cost 3 cache lines instead of 9
//  - main kernel: TWO samples per warp (16 lanes each) -> 12 pair-loads in
//    flight per warp, 4-step width-16 reduction, issue shared by 2 samples

#define BATCH      16384
#define NUM_FIELDS 10
#define FACTOR_DIM 8
#define INPUT_DIM  188610
#define NPAIRS     45
#define NPACKCOLS  8610        // fields 4..9: 5000+2000+1000+500+100+10
#define BLK_F      80          // floats per packed block (9*8 + w + pad)
#define BLK_B      (BLK_F*4)   // 320 bytes
#define W_OFF_B    288

__constant__ int c_off[NUM_FIELDS] = {
    0, 100000, 150000, 170000, 180000, 185000, 187000, 188000, 188500, 188600
};
__constant__ int c_pb[6] = { 0, 5000, 7000, 8000, 8500, 8600 };  // fields 4..9

__device__ __align__(128) float g_pack[NPACKCOLS * BLK_F];

// ---------------- pack kernel ----------------
__global__ __launch_bounds__(256) void pack_kernel(
    const float* __restrict__ w,
    const float* __restrict__ emb)
{
    int tid = blockIdx.x * blockDim.x + threadIdx.x;   // [0, 8610*20)
    if (tid >= NPACKCOLS * 20) return;
    int jp = tid / 20;
    int u  = tid % 20;
    int c4 = (jp >= 5000) + (jp >= 7000) + (jp >= 8000) + (jp >= 8500) + (jp >= 8600);
    int c  = 4 + c4;
    int col = c_off[c] + (jp - c_pb[c4]);

    if (u < 18) {
        int s = u >> 1, part = u & 1;
        int f = s + (s >= c);               // slot s holds field f (skip c)
        const float4 v = *reinterpret_cast<const float4*>(
            emb + ((size_t)f * INPUT_DIM + (size_t)col) * FACTOR_DIM + part * 4);
        *reinterpret_cast<float4*>(g_pack + (size_t)jp * BLK_F + s * 8 + part * 4) = v;
    } else if (u == 18) {
        g_pack[(size_t)jp * BLK_F + (W_OFF_B / 4)] = w[col];
    }
}

// ---------------- main kernel: 2 samples per warp ----------------
__global__ __launch_bounds__(256, 4) void ffm_kernel(
    const int*   __restrict__ x,       // (B, 10) int32
    const float* __restrict__ w,       // (INPUT_DIM,)
    const float* __restrict__ blin,    // scalar
    const float* __restrict__ emb,     // (10, INPUT_DIM, 8)
    float*       __restrict__ out)     // (B,)
{
    const unsigned FULL = 0xFFFFFFFFu;
    int wid  = (blockIdx.x * blockDim.x + threadIdx.x) >> 5;  // warp id
    int lane = threadIdx.x & 31;
    int h    = lane >> 4;              // sample half within warp
    int l16  = lane & 15;
    int b    = wid * 2 + h;            // sample id; grid sized exactly

    const char* pk = (const char*)g_pack;
    const char* eb = (const char*)emb;

    // Half-lane f (<10) owns field f of its sample. V = byte key:
    //   packed (f>=4): V = ~blockByteBase (negative); raw: V = xoff*32.
    int   V   = 0;
    float acc = 0.0f;
    if (l16 < NUM_FIELDS) {
        int xr = x[b * NUM_FIELDS + l16];
        if (l16 >= 4) {
            int pbb = (c_pb[l16 - 4] + xr) * BLK_B;
            V   = ~pbb;
            acc = *(const float*)(pk + pbb + W_OFF_B);    // w folded into block
        } else {
            V   = (xr + c_off[l16]) * 32;
            acc = w[xr + c_off[l16]];
        }
    }

    const int partB = (l16 & 1) << 4;  // 16B half select (t&1 == l16&1)

    float4 va[6], vb[6];
    bool   valid[6];

    #pragma unroll
    for (int k = 0; k < 6; k++) {
        int  t   = l16 + 16 * k;            // task id 0..95, 90 valid
        bool vld = t < 2 * NPAIRS;
        int  p   = vld ? (t >> 1) : 0;      // pair id (clamped: shfl convergence)

        // Pairs sorted by g DESC then f ASC; exact fp32 sqrt decode:
        // r = 45 - p; g = ceil((sqrt(8r+1)-1)/2); f = p - 45 + g(g+1)/2.
        int   r = NPAIRS - p;
        float s = sqrtf((float)(8 * r + 1));
        int   g = (int)ceilf((s - 1.0f) * 0.5f);
        int   f = p - NPAIRS + (g * (g + 1)) / 2;

        int vg = __shfl_sync(FULL, V, g, 16);   // key of A row: emb[f, x_g]
        int vf = __shfl_sync(FULL, V, f, 16);   // key of B row: emb[g, x_f]

        const char* pA = (vg < 0)
            ? (pk + (~vg) + f * 32)                               // slot f (f<g)
            : (eb + (unsigned)(f * (INPUT_DIM * 32)) + (unsigned)vg);
        const char* pB = (vf < 0)
            ? (pk + (~vf) + (g - 1) * 32)                         // slot g-1 (g>f)
            : (eb + (unsigned)(g * (INPUT_DIM * 32)) + (unsigned)vf);

        valid[k] = vld;
        if (vld) {
            va[k] = *(const float4*)(pA + partB);
            vb[k] = *(const float4*)(pB + partB);
        }
    }

    #pragma unroll
    for (int k = 0; k < 6; k++) {
        if (valid[k]) {
            acc += va[k].x * vb[k].x + va[k].y * vb[k].y
                 + va[k].z * vb[k].z + va[k].w * vb[k].w;
        }
    }

    // Reduction within each 16-lane half.
    #pragma unroll
    for (int o = 8; o > 0; o >>= 1)
        acc += __shfl_xor_sync(FULL, acc, o);

    if (l16 == 0)
        out[b] = acc + blin[0];
}

extern "C" void kernel_launch(void* const* d_in, const int* in_sizes, int n_in,
                              void* d_out, int out_size) {
    const int*   x    = (const int*)  d_in[0];
    const float* w    = (const float*)d_in[1];
    const float* blin = (const float*)d_in[2];
    const float* emb  = (const float*)d_in[3];
    float* out = (float*)d_out;

    const int pack_threads = 256;
    const int pack_blocks  = (NPACKCOLS * 20 + pack_threads - 1) / pack_threads;
    pack_kernel<<<pack_blocks, pack_threads>>>(w, emb);

    const int threads = 256;                      // 8 warps = 16 samples / block
    const int blocks  = (BATCH * 16) / threads;   // 1024
    ffm_kernel<<<blocks, threads>>>(x, w, blin, emb, out);
}

// round 13
// speedup vs baseline: 1.0075x; 1.0075x over previous
#include <cuda_runtime.h>
#include <cstdint>

// FieldAwareFM: B=16384, F=10 fields, D=8.
// y[b] = b_lin + sum_f w[xoff[b,f]] + sum_{f<g} <emb[f, xoff[b,g]], emb[g, xoff[b,f]]>
//
// Single kernel. FOUR samples per warp: 2 in parallel (16-lane halves) x
// 2 sequential pipelined iterations.
//  - 12 pair-loads in flight per warp per burst (best measured structure)
//  - x-indices for BOTH iterations prefetched up front: iteration 2's serial
//    prefix is hidden under iteration 1's gather burst
//  - grid = 512 blocks -> 4096 warps ~= one fully-resident wave (4 blocks/SM):
//    no second-wave prefix/tail, no wave transition
//  - task t = l16 + 16k -> (pair p = t>>1, 16B half = t&1); adjacent lanes read
//    the two halves of one 32B row inside ONE LDG (sector sharing)
//  - pairs ordered g-DESC/f-ASC via exact fp32 sqrt decode

#define BATCH      16384
#define NUM_FIELDS 10
#define FACTOR_DIM 8
#define INPUT_DIM  188610
#define NPAIRS     45

__constant__ int c_off[NUM_FIELDS] = {
    0, 100000, 150000, 170000, 180000, 185000, 187000, 188000, 188500, 188600
};

__global__ __launch_bounds__(256, 4) void ffm_kernel(
    const int*   __restrict__ x,       // (B, 10) int32
    const float* __restrict__ w,       // (INPUT_DIM,)
    const float* __restrict__ blin,    // scalar
    const float* __restrict__ emb,     // (10, INPUT_DIM, 8)
    float*       __restrict__ out)     // (B,)
{
    const unsigned FULL = 0xFFFFFFFFu;
    int wid  = (blockIdx.x * blockDim.x + threadIdx.x) >> 5;  // warp id
    int lane = threadIdx.x & 31;
    int h    = lane >> 4;              // sample half within warp
    int l16  = lane & 15;
    int bb   = wid * 4 + h;            // iteration 0 sample; iter 1 = bb+2

    const char* eb = (const char*)emb;
    const bool  fldlane = (l16 < NUM_FIELDS);

    // Prefetch raw x indices for BOTH iterations (coalesced: warp covers
    // 4 consecutive samples = 160 contiguous bytes).
    int xr0 = 0, xr1 = 0;
    if (fldlane) {
        xr0 = x[ bb      * NUM_FIELDS + l16];
        xr1 = x[(bb + 2) * NUM_FIELDS + l16];
    }

    const int   partB = (l16 & 1) << 4;  // 16B half select (t&1 == l16&1)
    const float bl    = blin[0];

    #pragma unroll
    for (int it = 0; it < 2; it++) {
        int b  = bb + it * 2;
        int xr = it ? xr1 : xr0;

        // Half-lane f (<10) owns field f. V = byte offset of column x_off
        // within a field plane (= xoff * 32).
        int   V   = 0;
        float acc = 0.0f;
        if (fldlane) {
            int xo = xr + c_off[l16];
            V   = xo * 32;
            acc = w[xo];
        }

        float4 va[6], vb[6];
        bool   valid[6];

        #pragma unroll
        for (int k = 0; k < 6; k++) {
            int  t   = l16 + 16 * k;            // task id 0..95, 90 valid
            bool vld = t < 2 * NPAIRS;
            int  p   = vld ? (t >> 1) : 0;      // pair id (clamped: shfl convergence)

            // Pairs sorted by g DESC then f ASC; exact fp32 sqrt decode:
            // r = 45 - p; g = ceil((sqrt(8r+1)-1)/2); f = p - 45 + g(g+1)/2.
            int   r = NPAIRS - p;
            float s = sqrtf((float)(8 * r + 1));
            int   g = (int)ceilf((s - 1.0f) * 0.5f);
            int   f = p - NPAIRS + (g * (g + 1)) / 2;

            int vg = __shfl_sync(FULL, V, g, 16);   // byte key of x_g
            int vf = __shfl_sync(FULL, V, f, 16);   // byte key of x_f

            // A row = emb[f, x_g], B row = emb[g, x_f]
            const char* pA = eb + (unsigned)(f * (INPUT_DIM * 32)) + (unsigned)vg;
            const char* pB = eb + (unsigned)(g * (INPUT_DIM * 32)) + (unsigned)vf;

            valid[k] = vld;
            if (vld) {
                va[k] = *(const float4*)(pA + partB);
                vb[k] = *(const float4*)(pB + partB);
            }
        }

        #pragma unroll
        for (int k = 0; k < 6; k++) {
            if (valid[k]) {
                acc += va[k].x * vb[k].x + va[k].y * vb[k].y
                     + va[k].z * vb[k].z + va[k].w * vb[k].w;
            }
        }

        // Reduction within each 16-lane half.
        #pragma unroll
        for (int o = 8; o > 0; o >>= 1)
            acc += __shfl_xor_sync(FULL, acc, o);

        if (l16 == 0)
            out[b] = acc + bl;
    }
}

extern "C" void kernel_launch(void* const* d_in, const int* in_sizes, int n_in,
                              void* d_out, int out_size) {
    const int*   x    = (const int*)  d_in[0];
    const float* w    = (const float*)d_in[1];
    const float* blin = (const float*)d_in[2];
    const float* emb  = (const float*)d_in[3];
    float* out = (float*)d_out;

    const int threads = 256;                      // 8 warps = 32 samples / block
    const int blocks  = (BATCH * 8) / threads;    // 512 -> one resident wave
    ffm_kernel<<<blocks, threads>>>(x, w, blin, emb, out);
}

// round 14
// speedup vs baseline: 1.0255x; 1.0179x over previous
#include <cuda_runtime.h>
#include <cstdint>

// FieldAwareFM: B=16384, F=10 fields, D=8.
// y[b] = b_lin + sum_f w[xoff[b,f]] + sum_{f<g} <emb[f, xoff[b,g]], emb[g, xoff[b,f]]>
//
// Best measured structure (12.768us): single kernel, TWO samples per warp
// (16-lane halves), 12 pair-loads in flight per warp, width-16 reduction,
// task t = l16 + 16k -> (pair p = t>>1, 16B half = t&1) with adjacent lanes
// sharing one 32B sector per LDG.
// Delta vs that kernel: the per-task sqrt/ceil pair decode is replaced by
// packed 4-bit-per-lane immediate tables (two shift+and per task, no MUFU).
// Pair order (g-DESC, f-ASC) is bit-identical to the sqrt version.

#define BATCH      16384
#define NUM_FIELDS 10
#define FACTOR_DIM 8
#define INPUT_DIM  188610
#define NPAIRS     45

__constant__ int c_off[NUM_FIELDS] = {
    0, 100000, 150000, 170000, 180000, 185000, 187000, 188000, 188500, 188600
};

// For k in 0..5, lane l16 in 0..15: nibble l16 of GTAB[k]/FTAB[k] = g/f of
// task t = l16 + 16k (p = t>>1), pairs enumerated g-DESC then f-ASC.
// k=5 lanes 10..15 are invalid tasks, clamped to (f=0,g=1).
__device__ __constant__ unsigned long long GTAB_[6];  // unused placeholder (kept out of const bank pressure)

#define GTAB0 0x9999999999999999ULL
#define GTAB1 0x8888888888888899ULL
#define GTAB2 0x7777777777777788ULL
#define GTAB3 0x5555666666666666ULL
#define GTAB4 0x3344444444555555ULL
#define GTAB5 0x1111111122223333ULL

#define FTAB0 0x7766554433221100ULL
#define FTAB1 0x6655443322110088ULL
#define FTAB2 0x6655443322110077ULL
#define FTAB3 0x1100554433221100ULL
#define FTAB4 0x0033221100443322ULL
#define FTAB5 0x0000000011002211ULL

__global__ __launch_bounds__(256, 4) void ffm_kernel(
    const int*   __restrict__ x,       // (B, 10) int32
    const float* __restrict__ w,       // (INPUT_DIM,)
    const float* __restrict__ blin,    // scalar
    const float* __restrict__ emb,     // (10, INPUT_DIM, 8)
    float*       __restrict__ out)     // (B,)
{
    const unsigned FULL = 0xFFFFFFFFu;
    int wid  = (blockIdx.x * blockDim.x + threadIdx.x) >> 5;  // warp id
    int lane = threadIdx.x & 31;
    int h    = lane >> 4;              // sample half within warp
    int l16  = lane & 15;
    int b    = wid * 2 + h;            // sample id; grid sized exactly

    const char* eb = (const char*)emb;

    // Half-lane f (<10) owns field f of its sample.
    // V = byte offset of column x_off within one field-plane (= xoff * 32).
    int   V   = 0;
    float acc = 0.0f;
    if (l16 < NUM_FIELDS) {
        int xo = x[b * NUM_FIELDS + l16] + c_off[l16];
        V   = xo * 32;
        acc = w[xo];
    }

    const int partB = (l16 & 1) << 4;  // 16B half select (t&1 == l16&1)
    const int sh    = l16 * 4;         // nibble shift for this lane

    const unsigned long long GT[6] = { GTAB0, GTAB1, GTAB2, GTAB3, GTAB4, GTAB5 };
    const unsigned long long FT[6] = { FTAB0, FTAB1, FTAB2, FTAB3, FTAB4, FTAB5 };

    float4 va[6], vb[6];
    bool   valid[6];

    #pragma unroll
    for (int k = 0; k < 6; k++) {
        // Immediate-table decode: g, f for task t = l16 + 16k.
        int g = (int)((GT[k] >> sh) & 15);
        int f = (int)((FT[k] >> sh) & 15);

        int vg = __shfl_sync(FULL, V, g, 16);   // byte key of x_g
        int vf = __shfl_sync(FULL, V, f, 16);   // byte key of x_f

        // A row = emb[f, x_g], B row = emb[g, x_f]
        const char* pA = eb + (unsigned)(f * (INPUT_DIM * 32)) + (unsigned)vg;
        const char* pB = eb + (unsigned)(g * (INPUT_DIM * 32)) + (unsigned)vf;

        valid[k] = (k < 5) | (l16 < 10);        // only k=5, l16>=10 invalid
        if (valid[k]) {
            va[k] = *(const float4*)(pA + partB);
            vb[k] = *(const float4*)(pB + partB);
        }
    }

    #pragma unroll
    for (int k = 0; k < 6; k++) {
        if (valid[k]) {
            acc += va[k].x * vb[k].x + va[k].y * vb[k].y
                 + va[k].z * vb[k].z + va[k].w * vb[k].w;
        }
    }

    // Reduction within each 16-lane half.
    #pragma unroll
    for (int o = 8; o > 0; o >>= 1)
        acc += __shfl_xor_sync(FULL, acc, o);

    if (l16 == 0)
        out[b] = acc + blin[0];
}

extern "C" void kernel_launch(void* const* d_in, const int* in_sizes, int n_in,
                              void* d_out, int out_size) {
    const int*   x    = (const int*)  d_in[0];
    const float* w    = (const float*)d_in[1];
    const float* blin = (const float*)d_in[2];
    const float* emb  = (const float*)d_in[3];
    float* out = (float*)d_out;

    const int threads = 256;                      // 8 warps = 16 samples / block
    const int blocks  = (BATCH * 16) / threads;   // 1024
    ffm_kernel<<<blocks, threads>>>(x, w, blin, emb, out);
}